// round 16
// baseline (speedup 1.0000x reference)
#include <cuda_runtime.h>
#include <math.h>

// ---------------- problem constants ----------------
#define T_      4096
#define DIM_    1024
#define HEADS_  16
#define DH_     64
#define NH_     8
#define NB_     64
#define BUCKET_ 64
#define MB      32                 // merged batch*heads = 2*16
#define NT      (NH_*T_)           // 32768
#define NCH     (NH_*NB_)          // 512 chunks per merged batch

// ---------------- scratch (device globals; no allocs allowed) ----------------
__device__ float g_qk  [2*T_*DIM_];            // 33.5 MB
__device__ float g_v   [2*T_*DIM_];            // 33.5 MB
__device__ float g_comb[2*T_*DIM_];            // 33.5 MB
__device__ float g_invn[MB*T_];
__device__ int   g_bucket[MB*NH_*T_];          // local bucket (0..63)
__device__ int   g_st [MB*NT];                 // sorted token index
__device__ unsigned short g_pos[MB*NH_*T_];    // round-local sorted position of token
__device__ float g_so [(size_t)MB*NT*DH_];     // 268 MB
__device__ float g_lse[MB*NT];

__device__ __forceinline__ size_t tok_off(int m, int t) {
    // merged index m = b*16 + head; full tensor layout [b][t][head*64+d]
    return ((size_t)((m >> 4) * T_ + t)) * DIM_ + (size_t)((m & 15) * DH_);
}

// ---------------- fp32 SGEMM: C[i][o] = sum_k A[i][k]*W[o][k] (+bias) ----------------
// 128x128 tile, BK=8, 256 threads, 8x8 per thread.
// Software-pipelined: next K-tile's global loads issue before the compute block.
__global__ void sgemm_xwT(const float* __restrict__ A, const float* __restrict__ W,
                          const float* __restrict__ bias, float* __restrict__ C,
                          int M, int N, int K, int hasBias) {
    __shared__ float As[8][128];
    __shared__ float Ws[8][128];
    const int tid = threadIdx.x;
    const int row0 = blockIdx.y * 128;
    const int col0 = blockIdx.x * 128;
    const int ty = tid >> 4, tx = tid & 15;

    float acc[8][8];
#pragma unroll
    for (int r = 0; r < 8; r++)
#pragma unroll
        for (int c = 0; c < 8; c++) acc[r][c] = 0.f;

    const int lr = tid >> 1;          // 0..127
    const int lk = (tid & 1) * 4;     // 0 or 4
    const float* Aptr = A + (size_t)(row0 + lr) * K + lk;
    const float* Wptr = W + (size_t)(col0 + lr) * K + lk;

    // prologue: load first K-tile into registers
    float4 av = *(const float4*)(Aptr);
    float4 wv = *(const float4*)(Wptr);

    for (int kt = 0; kt < K; kt += 8) {
        // commit current tile to smem
        As[lk + 0][lr] = av.x; As[lk + 1][lr] = av.y;
        As[lk + 2][lr] = av.z; As[lk + 3][lr] = av.w;
        Ws[lk + 0][lr] = wv.x; Ws[lk + 1][lr] = wv.y;
        Ws[lk + 2][lr] = wv.z; Ws[lk + 3][lr] = wv.w;
        __syncthreads();

        // prefetch next tile (overlaps with compute below)
        if (kt + 8 < K) {
            av = *(const float4*)(Aptr + kt + 8);
            wv = *(const float4*)(Wptr + kt + 8);
        }

#pragma unroll
        for (int kk = 0; kk < 8; kk++) {
            float a[8], b[8];
#pragma unroll
            for (int r = 0; r < 8; r++) a[r] = As[kk][ty * 8 + r];
#pragma unroll
            for (int c = 0; c < 8; c++) b[c] = Ws[kk][tx * 8 + c];
#pragma unroll
            for (int r = 0; r < 8; r++)
#pragma unroll
                for (int c = 0; c < 8; c++) acc[r][c] += a[r] * b[c];
        }
        __syncthreads();
    }

#pragma unroll
    for (int r = 0; r < 8; r++) {
        int row = row0 + ty * 8 + r;
        float* crow = C + (size_t)row * N + col0 + tx * 8;
#pragma unroll
        for (int cg = 0; cg < 2; cg++) {
            int cc = cg * 4;
            float4 o;
            o.x = acc[r][cc + 0]; o.y = acc[r][cc + 1];
            o.z = acc[r][cc + 2]; o.w = acc[r][cc + 3];
            if (hasBias) {
                int col = col0 + tx * 8 + cc;
                o.x += bias[col + 0]; o.y += bias[col + 1];
                o.z += bias[col + 2]; o.w += bias[col + 3];
            }
            ((float4*)crow)[cg] = o;
        }
    }
}

// ---------------- per-token inverse key norm ----------------
__global__ void invnorm_kernel() {
    int idx = blockIdx.x * 256 + threadIdx.x;      // idx = m*T_ + t
    int m = idx >> 12, t = idx & (T_ - 1);
    const float4* p = (const float4*)(g_qk + tok_off(m, t));
    float s = 0.f;
#pragma unroll
    for (int q = 0; q < 16; q++) {
        float4 v = p[q];
        s += v.x * v.x + v.y * v.y + v.z * v.z + v.w * v.w;
    }
    g_invn[idx] = 1.f / fmaxf(sqrtf(s), 1e-12f);
}

// ---------------- LSH hashing: bucket = argmax over [rot, -rot] ----------------
// grid (T_/16, MB), 256 threads; warp = hash round h, lane = projection i.
__global__ void hash_kernel(const float* __restrict__ rot) {
    __shared__ float sq[16][64];
    int tid = threadIdx.x;
    int m = blockIdx.y, t0 = blockIdx.x * 16;
    const float* qkbase = g_qk + tok_off(m, t0);
#pragma unroll
    for (int r = 0; r < 4; r++) {
        int idx = r * 256 + tid;
        int j = idx >> 6, d = idx & 63;
        sq[j][d] = qkbase[(size_t)j * DIM_ + d];
    }
    __syncthreads();

    int h = tid >> 5, lane = tid & 31;
    // preload this lane's rotation column: rotations[f][h][lane]
    float rv[64];
    const float* rp = rot + h * 32 + lane;
#pragma unroll
    for (int f = 0; f < 64; f++) rv[f] = rp[f * 256];

    for (int j = 0; j < 16; j++) {
        float acc = 0.f;
#pragma unroll
        for (int f = 0; f < 64; f++) acc += sq[j][f] * rv[f];
        float bv = acc; int bi = lane;
        if (-acc > bv) { bv = -acc; bi = lane + 32; }   // strict > : +rot wins ties (argmax picks first)
#pragma unroll
        for (int off = 16; off; off >>= 1) {
            float ov = __shfl_down_sync(0xffffffffu, bv, off);
            int   oi = __shfl_down_sync(0xffffffffu, bi, off);
            if (ov > bv || (ov == bv && oi < bi)) { bv = ov; bi = oi; }
        }
        if (lane == 0) g_bucket[(m * NH_ + h) * T_ + t0 + j] = bi;
    }
}

// ---------------- exact stable counting sort per (m,h) ----------------
// Reproduces argsort(T*bucket + t) exactly: counting sort by bucket, stable in t.
__global__ void sort_kernel() {
    __shared__ unsigned short hist[256][64];
    __shared__ int tot[64];
    __shared__ int base_[64];
    __shared__ int psum[4][64];
    int tid = threadIdx.x;
    int mh = blockIdx.x;                       // m*8 + h
    const int* buck = g_bucket + mh * T_;

    for (int k = 0; k < 64; k++) hist[tid][k] = 0;
    __syncthreads();

    int t0 = tid * 16;
#pragma unroll
    for (int j = 0; j < 16; j++) hist[tid][buck[t0 + j]]++;
    __syncthreads();

    if (tid < 64) {
        int s = 0;
        for (int th = 0; th < 256; th++) s += hist[th][tid];
        tot[tid] = s;
    }
    __syncthreads();
    if (tid == 0) {
        int s = 0;
        for (int k = 0; k < 64; k++) { base_[k] = s; s += tot[k]; }
    }
    __syncthreads();

    int g = tid >> 6, bk = tid & 63;           // 4 groups x 64 buckets
    {
        int s = 0;
        for (int th = g * 64; th < g * 64 + 64; th++) {
            int vv = hist[th][bk];
            hist[th][bk] = (unsigned short)s;
            s += vv;
        }
        psum[g][bk] = s;
    }
    __syncthreads();
    {
        int add = base_[bk];
        for (int gg = 0; gg < g; gg++) add += psum[gg][bk];
        for (int th = g * 64; th < g * 64 + 64; th++)
            hist[th][bk] = (unsigned short)(hist[th][bk] + add);
    }
    __syncthreads();

    int m = mh >> 3, h = mh & 7;
    int* stp = g_st + m * NT + h * T_;
    unsigned short* pp = g_pos + mh * T_;
#pragma unroll
    for (int j = 0; j < 16; j++) {
        int t = t0 + j;
        int b = buck[t];
        int p = hist[tid][b];
        hist[tid][b] = (unsigned short)(p + 1);   // private row -> t-ordered, stable
        stp[p] = t;
        pp[t] = (unsigned short)p;
    }
}

// ---------------- chunk-local attention ----------------
// grid (NCH, MB), 256 threads (8 warps), dynamic smem.
#define SQ_OFF   0
#define SK_OFF   4096                // sq: 64*64
#define SV_OFF   (SK_OFF + 128*65)   // sk: 128 rows, stride 65 (bank pad)
#define DT_OFF   (SV_OFF + 128*64)   // sv: 128*64
#define F_TOTAL  (DT_OFF + 64*129)   // dots: 64 rows, stride 129 (bank pad)
#define ATTN_SMEM (F_TOTAL*4 + 192*4)

__global__ void attn_kernel() {
    extern __shared__ float sh[];
    float* sq   = sh + SQ_OFF;
    float* sk   = sh + SK_OFF;
    float* sv   = sh + SV_OFF;
    float* dots = sh + DT_OFF;
    int* qt = (int*)(sh + F_TOTAL);
    int* kt = qt + 64;

    const int tid = threadIdx.x;            // 0..255
    const int c = blockIdx.x, m = blockIdx.y;
    const int base = m * NT;

    if (tid < 64) qt[tid] = g_st[base + c * 64 + tid];
    if (tid < 128) {
        int ck = (tid < 64) ? c : ((c + NCH - 1) & (NCH - 1));   // look-one-back (wraps all 512 chunks)
        kt[tid] = g_st[base + ck * 64 + (tid & 63)];
    }
    __syncthreads();

    // load q tile: 64 rows x 64 d as float4 (1024 float4, 256 threads x 4)
#pragma unroll
    for (int r = 0; r < 4; r++) {
        int idx4 = r * 256 + tid;            // 0..1023
        int i = idx4 >> 4, dq = (idx4 & 15) * 4;
        float4 v = *(const float4*)(g_qk + tok_off(m, qt[i]) + dq);
        sq[i * 64 + dq + 0] = v.x; sq[i * 64 + dq + 1] = v.y;
        sq[i * 64 + dq + 2] = v.z; sq[i * 64 + dq + 3] = v.w;
    }
    // load k (normalized) and v tiles: 128 rows x 64 d as float4 (2048 float4)
#pragma unroll
    for (int r = 0; r < 8; r++) {
        int idx4 = r * 256 + tid;            // 0..2047
        int j = idx4 >> 4, dq = (idx4 & 15) * 4;
        int t = kt[j];
        size_t off = tok_off(m, t) + dq;
        float inm = g_invn[m * T_ + t];
        float4 kq = *(const float4*)(g_qk + off);
        float4 vq = *(const float4*)(g_v + off);
        sk[j * 65 + dq + 0] = kq.x * inm; sk[j * 65 + dq + 1] = kq.y * inm;
        sk[j * 65 + dq + 2] = kq.z * inm; sk[j * 65 + dq + 3] = kq.w * inm;
        *(float4*)(sv + j * 64 + dq) = vq;
    }
    __syncthreads();

    // phase 1: dots — thread owns (key column j = tid&127, row-half rh = tid>>7).
    // Same per-dot accumulation order over d as before -> bit-identical.
    {
        const int j = tid & 127;
        const int i0 = (tid >> 7) * 32;      // rows i0..i0+31
        float kr[64];
#pragma unroll
        for (int d = 0; d < 64; d++) kr[d] = sk[j * 65 + d];
        int mykt = kt[j];
        for (int i = i0; i < i0 + 32; i += 4) {
            float a0 = 0.f, a1 = 0.f, a2 = 0.f, a3 = 0.f;
#pragma unroll
            for (int d = 0; d < 64; d++) {
                float k = kr[d];
                a0 += sq[(i + 0) * 64 + d] * k;
                a1 += sq[(i + 1) * 64 + d] * k;
                a2 += sq[(i + 2) * 64 + d] * k;
                a3 += sq[(i + 3) * 64 + d] * k;
            }
            a0 *= 0.125f; a1 *= 0.125f; a2 *= 0.125f; a3 *= 0.125f;
            if (qt[i + 0] == mykt) a0 = -50000.0f;
            if (qt[i + 1] == mykt) a1 = -50000.0f;
            if (qt[i + 2] == mykt) a2 = -50000.0f;
            if (qt[i + 3] == mykt) a3 = -50000.0f;
            dots[(i + 0) * 129 + j] = a0;
            dots[(i + 1) * 129 + j] = a1;
            dots[(i + 2) * 129 + j] = a2;
            dots[(i + 3) * 129 + j] = a3;
        }
    }
    __syncthreads();

    // phase 2: softmax + PV, one pass over j. Thread owns (row i = tid&63, d-quarter).
    // o = (1/s) * sum_j exp(d_j - mx) v_j  ==  sum_j exp(d_j - lse) v_j
    {
        int i = tid & 63, quarter = tid >> 6;    // 0..3, 16 d-elements each
        float mx = -1e30f;
        for (int j = 0; j < 128; j++) mx = fmaxf(mx, dots[i * 129 + j]);

        float s = 0.f;
        float acc[16];
#pragma unroll
        for (int d = 0; d < 16; d++) acc[d] = 0.f;
        for (int j = 0; j < 128; j++) {
            float w = expf(dots[i * 129 + j] - mx);
            s += w;
            const float* vv = &sv[j * 64 + quarter * 16];
#pragma unroll
            for (int d = 0; d < 16; d++) acc[d] += w * vv[d];
        }
        float inv = 1.f / s;
#pragma unroll
        for (int d = 0; d < 16; d++) acc[d] *= inv;

        size_t ro = ((size_t)(base + c * 64 + i)) * 64 + quarter * 16;
        float4* dst = (float4*)(g_so + ro);
#pragma unroll
        for (int q = 0; q < 4; q++)
            dst[q] = make_float4(acc[4 * q], acc[4 * q + 1], acc[4 * q + 2], acc[4 * q + 3]);
        if (quarter == 0) g_lse[base + c * 64 + i] = mx + logf(s);
    }
}

// ---------------- combine hash rounds (softmax over per-round LSE) ----------------
__global__ void combine_kernel() {
    int idx = blockIdx.x * 256 + threadIdx.x;      // m*T_ + t
    int m = idx >> 12, t = idx & (T_ - 1);

    float lg[8]; int gp[8];
#pragma unroll
    for (int h = 0; h < 8; h++) {
        int p = g_pos[(m * NH_ + h) * T_ + t];
        gp[h] = h * T_ + p;
        lg[h] = g_lse[m * NT + gp[h]];
    }
    float mx = lg[0];
#pragma unroll
    for (int h = 1; h < 8; h++) mx = fmaxf(mx, lg[h]);
    float s = 0.f; float w[8];
#pragma unroll
    for (int h = 0; h < 8; h++) { w[h] = expf(lg[h] - mx); s += w[h]; }
    float inv = 1.f / s;

    float out[64];
#pragma unroll
    for (int d = 0; d < 64; d++) out[d] = 0.f;
#pragma unroll
    for (int h = 0; h < 8; h++) {
        const float4* src = (const float4*)(g_so + ((size_t)(m * NT + gp[h])) * 64);
        float ww = w[h] * inv;
#pragma unroll
        for (int q = 0; q < 16; q++) {
            float4 v = src[q];
            out[4 * q + 0] += ww * v.x;
            out[4 * q + 1] += ww * v.y;
            out[4 * q + 2] += ww * v.z;
            out[4 * q + 3] += ww * v.w;
        }
    }
    float4* dst = (float4*)(g_comb + tok_off(m, t));
#pragma unroll
    for (int q = 0; q < 16; q++)
        dst[q] = make_float4(out[4 * q], out[4 * q + 1], out[4 * q + 2], out[4 * q + 3]);
}

// ---------------- launch ----------------
extern "C" void kernel_launch(void* const* d_in, const int* in_sizes, int n_in,
                              void* d_out, int out_size) {
    const float* x     = (const float*)d_in[0];
    const float* w_qk  = (const float*)d_in[1];
    const float* w_v   = (const float*)d_in[2];
    const float* w_out = (const float*)d_in[3];
    const float* b_out = (const float*)d_in[4];
    const float* rot   = (const float*)d_in[5];
    float* out = (float*)d_out;

    float *p_qk, *p_v, *p_comb;
    cudaGetSymbolAddress((void**)&p_qk,   g_qk);
    cudaGetSymbolAddress((void**)&p_v,    g_v);
    cudaGetSymbolAddress((void**)&p_comb, g_comb);

    cudaFuncSetAttribute(attn_kernel, cudaFuncAttributeMaxDynamicSharedMemorySize, ATTN_SMEM);

    dim3 gb(DIM_ / 128, (2 * T_) / 128);   // (8, 64)
    sgemm_xwT<<<gb, 256>>>(x, w_qk, nullptr, p_qk, 2 * T_, DIM_, DIM_, 0);
    sgemm_xwT<<<gb, 256>>>(x, w_v,  nullptr, p_v,  2 * T_, DIM_, DIM_, 0);

    invnorm_kernel<<<(MB * T_) / 256, 256>>>();
    hash_kernel<<<dim3(T_ / 16, MB), 256>>>(rot);
    sort_kernel<<<MB * NH_, 256>>>();

    attn_kernel<<<dim3(NCH, MB), 256, ATTN_SMEM>>>();

    combine_kernel<<<(MB * T_) / 256, 256>>>();
    sgemm_xwT<<<gb, 256>>>(p_comb, w_out, b_out, out, 2 * T_, DIM_, DIM_, 1);
}

// round 17
// speedup vs baseline: 1.0231x; 1.0231x over previous
#include <cuda_runtime.h>
#include <math.h>
#include <mma.h>

using namespace nvcuda;

// ---------------- problem constants ----------------
#define T_      4096
#define DIM_    1024
#define HEADS_  16
#define DH_     64
#define NH_     8
#define NB_     64
#define BUCKET_ 64
#define MB      32                 // merged batch*heads = 2*16
#define NT      (NH_*T_)           // 32768
#define NCH     (NH_*NB_)          // 512 chunks per merged batch

// ---------------- scratch (device globals; no allocs allowed) ----------------
__device__ float g_qk  [2*T_*DIM_];            // 33.5 MB
__device__ float g_v   [2*T_*DIM_];            // 33.5 MB
__device__ float g_comb[2*T_*DIM_];            // 33.5 MB
__device__ float g_invn[MB*T_];
__device__ int   g_bucket[MB*NH_*T_];          // local bucket (0..63)
__device__ int   g_st [MB*NT];                 // sorted token index
__device__ unsigned short g_pos[MB*NH_*T_];    // round-local sorted position of token
__device__ float g_so [(size_t)MB*NT*DH_];     // 268 MB
__device__ float g_lse[MB*NT];

__device__ __forceinline__ size_t tok_off(int m, int t) {
    // merged index m = b*16 + head; full tensor layout [b][t][head*64+d]
    return ((size_t)((m >> 4) * T_ + t)) * DIM_ + (size_t)((m & 15) * DH_);
}

// ---------------- fp32 SGEMM: C[i][o] = sum_k A[i][k]*W[o][k] (+bias) ----------------
// 128x128 tile, BK=8, 256 threads, 8x8 per thread. Software-pipelined.
__global__ void sgemm_xwT(const float* __restrict__ A, const float* __restrict__ W,
                          const float* __restrict__ bias, float* __restrict__ C,
                          int M, int N, int K, int hasBias) {
    __shared__ float As[8][128];
    __shared__ float Ws[8][128];
    const int tid = threadIdx.x;
    const int row0 = blockIdx.y * 128;
    const int col0 = blockIdx.x * 128;
    const int ty = tid >> 4, tx = tid & 15;

    float acc[8][8];
#pragma unroll
    for (int r = 0; r < 8; r++)
#pragma unroll
        for (int c = 0; c < 8; c++) acc[r][c] = 0.f;

    const int lr = tid >> 1;          // 0..127
    const int lk = (tid & 1) * 4;     // 0 or 4
    const float* Aptr = A + (size_t)(row0 + lr) * K + lk;
    const float* Wptr = W + (size_t)(col0 + lr) * K + lk;

    float4 av = *(const float4*)(Aptr);
    float4 wv = *(const float4*)(Wptr);

    for (int kt = 0; kt < K; kt += 8) {
        As[lk + 0][lr] = av.x; As[lk + 1][lr] = av.y;
        As[lk + 2][lr] = av.z; As[lk + 3][lr] = av.w;
        Ws[lk + 0][lr] = wv.x; Ws[lk + 1][lr] = wv.y;
        Ws[lk + 2][lr] = wv.z; Ws[lk + 3][lr] = wv.w;
        __syncthreads();

        if (kt + 8 < K) {
            av = *(const float4*)(Aptr + kt + 8);
            wv = *(const float4*)(Wptr + kt + 8);
        }

#pragma unroll
        for (int kk = 0; kk < 8; kk++) {
            float a[8], b[8];
#pragma unroll
            for (int r = 0; r < 8; r++) a[r] = As[kk][ty * 8 + r];
#pragma unroll
            for (int c = 0; c < 8; c++) b[c] = Ws[kk][tx * 8 + c];
#pragma unroll
            for (int r = 0; r < 8; r++)
#pragma unroll
                for (int c = 0; c < 8; c++) acc[r][c] += a[r] * b[c];
        }
        __syncthreads();
    }

#pragma unroll
    for (int r = 0; r < 8; r++) {
        int row = row0 + ty * 8 + r;
        float* crow = C + (size_t)row * N + col0 + tx * 8;
#pragma unroll
        for (int cg = 0; cg < 2; cg++) {
            int cc = cg * 4;
            float4 o;
            o.x = acc[r][cc + 0]; o.y = acc[r][cc + 1];
            o.z = acc[r][cc + 2]; o.w = acc[r][cc + 3];
            if (hasBias) {
                int col = col0 + tx * 8 + cc;
                o.x += bias[col + 0]; o.y += bias[col + 1];
                o.z += bias[col + 2]; o.w += bias[col + 3];
            }
            ((float4*)crow)[cg] = o;
        }
    }
}

// ---------------- per-token inverse key norm ----------------
__global__ void invnorm_kernel() {
    int idx = blockIdx.x * 256 + threadIdx.x;      // idx = m*T_ + t
    int m = idx >> 12, t = idx & (T_ - 1);
    const float4* p = (const float4*)(g_qk + tok_off(m, t));
    float s = 0.f;
#pragma unroll
    for (int q = 0; q < 16; q++) {
        float4 v = p[q];
        s += v.x * v.x + v.y * v.y + v.z * v.z + v.w * v.w;
    }
    g_invn[idx] = 1.f / fmaxf(sqrtf(s), 1e-12f);
}

// ---------------- LSH hashing: bucket = argmax over [rot, -rot] ----------------
// grid (T_/64, MB), 256 threads; warp = hash round h, lane = projection i.
// 64 tokens per block amortizes the 64-float/lane rotation register load 4x
// (was the measured L1 bottleneck: 80.8% L1 at 16 tokens/block).
__global__ void hash_kernel(const float* __restrict__ rot) {
    __shared__ float sq[64][64];                   // 16 KB
    int tid = threadIdx.x;
    int m = blockIdx.y, t0 = blockIdx.x * 64;
    const float* qkbase = g_qk + tok_off(m, t0);
#pragma unroll
    for (int r = 0; r < 16; r++) {
        int idx = r * 256 + tid;
        int j = idx >> 6, d = idx & 63;
        sq[j][d] = qkbase[(size_t)j * DIM_ + d];
    }
    __syncthreads();

    int h = tid >> 5, lane = tid & 31;
    // preload this lane's rotation column: rotations[f][h][lane]
    float rv[64];
    const float* rp = rot + h * 32 + lane;
#pragma unroll
    for (int f = 0; f < 64; f++) rv[f] = rp[f * 256];

    for (int j = 0; j < 64; j++) {
        float acc = 0.f;
#pragma unroll
        for (int f = 0; f < 64; f++) acc += sq[j][f] * rv[f];
        float bv = acc; int bi = lane;
        if (-acc > bv) { bv = -acc; bi = lane + 32; }   // strict > : +rot wins ties (argmax picks first)
#pragma unroll
        for (int off = 16; off; off >>= 1) {
            float ov = __shfl_down_sync(0xffffffffu, bv, off);
            int   oi = __shfl_down_sync(0xffffffffu, bi, off);
            if (ov > bv || (ov == bv && oi < bi)) { bv = ov; bi = oi; }
        }
        if (lane == 0) g_bucket[(m * NH_ + h) * T_ + t0 + j] = bi;
    }
}

// ---------------- exact stable counting sort per (m,h) ----------------
// Reproduces argsort(T*bucket + t) exactly: counting sort by bucket, stable in t.
__global__ void sort_kernel() {
    __shared__ unsigned short hist[256][64];
    __shared__ int tot[64];
    __shared__ int base_[64];
    __shared__ int psum[4][64];
    int tid = threadIdx.x;
    int mh = blockIdx.x;                       // m*8 + h
    const int* buck = g_bucket + mh * T_;

    for (int k = 0; k < 64; k++) hist[tid][k] = 0;
    __syncthreads();

    int t0 = tid * 16;
#pragma unroll
    for (int j = 0; j < 16; j++) hist[tid][buck[t0 + j]]++;
    __syncthreads();

    if (tid < 64) {
        int s = 0;
        for (int th = 0; th < 256; th++) s += hist[th][tid];
        tot[tid] = s;
    }
    __syncthreads();
    if (tid == 0) {
        int s = 0;
        for (int k = 0; k < 64; k++) { base_[k] = s; s += tot[k]; }
    }
    __syncthreads();

    int g = tid >> 6, bk = tid & 63;           // 4 groups x 64 buckets
    {
        int s = 0;
        for (int th = g * 64; th < g * 64 + 64; th++) {
            int vv = hist[th][bk];
            hist[th][bk] = (unsigned short)s;
            s += vv;
        }
        psum[g][bk] = s;
    }
    __syncthreads();
    {
        int add = base_[bk];
        for (int gg = 0; gg < g; gg++) add += psum[gg][bk];
        for (int th = g * 64; th < g * 64 + 64; th++)
            hist[th][bk] = (unsigned short)(hist[th][bk] + add);
    }
    __syncthreads();

    int m = mh >> 3, h = mh & 7;
    int* stp = g_st + m * NT + h * T_;
    unsigned short* pp = g_pos + mh * T_;
#pragma unroll
    for (int j = 0; j < 16; j++) {
        int t = t0 + j;
        int b = buck[t];
        int p = hist[tid][b];
        hist[tid][b] = (unsigned short)(p + 1);   // private row -> t-ordered, stable
        stp[p] = t;
        pp[t] = (unsigned short)p;
    }
}

// ---------------- chunk-local attention ----------------
// grid (NCH, MB), 256 threads (8 warps), dynamic smem.
// Phase 1 = WMMA TF32 (m16n16k8); strides chosen for wmma ldm%4==0.
#define SQ_OFF   0
#define SK_OFF   4096                // sq: 64*64
#define SV_OFF   (SK_OFF + 128*68)   // sk: 128 rows, stride 68 (wmma ldm%4, bank offset 4)
#define DT_OFF   (SV_OFF + 128*64)   // sv: 128*64
#define F_TOTAL  (DT_OFF + 64*132)   // dots: 64 rows, stride 132 (wmma ldm%4)
#define ATTN_SMEM (F_TOTAL*4 + 192*4)

__global__ void attn_kernel() {
    extern __shared__ float sh[];
    float* sq   = sh + SQ_OFF;
    float* sk   = sh + SK_OFF;
    float* sv   = sh + SV_OFF;
    float* dots = sh + DT_OFF;
    int* qt = (int*)(sh + F_TOTAL);
    int* kt = qt + 64;

    const int tid = threadIdx.x;            // 0..255
    const int c = blockIdx.x, m = blockIdx.y;
    const int base = m * NT;

    if (tid < 64) qt[tid] = g_st[base + c * 64 + tid];
    if (tid < 128) {
        int ck = (tid < 64) ? c : ((c + NCH - 1) & (NCH - 1));   // look-one-back (wraps all 512 chunks)
        kt[tid] = g_st[base + ck * 64 + (tid & 63)];
    }
    __syncthreads();

    // load q tile: 64 rows x 64 d as float4
#pragma unroll
    for (int r = 0; r < 4; r++) {
        int idx4 = r * 256 + tid;            // 0..1023
        int i = idx4 >> 4, dq = (idx4 & 15) * 4;
        float4 v = *(const float4*)(g_qk + tok_off(m, qt[i]) + dq);
        sq[i * 64 + dq + 0] = v.x; sq[i * 64 + dq + 1] = v.y;
        sq[i * 64 + dq + 2] = v.z; sq[i * 64 + dq + 3] = v.w;
    }
    // load k (normalized) and v tiles: 128 rows x 64 d as float4
#pragma unroll
    for (int r = 0; r < 8; r++) {
        int idx4 = r * 256 + tid;            // 0..2047
        int j = idx4 >> 4, dq = (idx4 & 15) * 4;
        int t = kt[j];
        size_t off = tok_off(m, t) + dq;
        float inm = g_invn[m * T_ + t];
        float4 kq = *(const float4*)(g_qk + off);
        float4 vq = *(const float4*)(g_v + off);
        sk[j * 68 + dq + 0] = kq.x * inm; sk[j * 68 + dq + 1] = kq.y * inm;
        sk[j * 68 + dq + 2] = kq.z * inm; sk[j * 68 + dq + 3] = kq.w * inm;
        *(float4*)(sv + j * 64 + dq) = vq;
    }
    __syncthreads();

    // phase 1: dots = Q @ K^T via WMMA TF32.
    // Output 64x128 = 4 row-tiles x 8 col-tiles of 16x16; warp w does
    // row-tile (w>>1) x col-tiles [(w&1)*4, +4), K loop of 8 k8-steps.
    {
        const int w   = tid >> 5;
        const int rt  = w >> 1;
        const int ct0 = (w & 1) * 4;

        wmma::fragment<wmma::matrix_a, 16, 16, 8, wmma::precision::tf32, wmma::row_major> afrag[8];
#pragma unroll
        for (int k = 0; k < 8; k++) {
            wmma::load_matrix_sync(afrag[k], sq + rt * 16 * 64 + k * 8, 64);
#pragma unroll
            for (int t = 0; t < afrag[k].num_elements; t++)
                afrag[k].x[t] = wmma::__float_to_tf32(afrag[k].x[t]);
        }
#pragma unroll
        for (int cc = 0; cc < 4; cc++) {
            int ct = ct0 + cc;
            wmma::fragment<wmma::accumulator, 16, 16, 8, float> acc;
            wmma::fill_fragment(acc, 0.0f);
#pragma unroll
            for (int k = 0; k < 8; k++) {
                wmma::fragment<wmma::matrix_b, 16, 16, 8, wmma::precision::tf32, wmma::col_major> bfrag;
                // B(d, j) = sk[j*68 + d] -> col_major, ldm 68
                wmma::load_matrix_sync(bfrag, sk + ct * 16 * 68 + k * 8, 68);
#pragma unroll
                for (int t = 0; t < bfrag.num_elements; t++)
                    bfrag.x[t] = wmma::__float_to_tf32(bfrag.x[t]);
                wmma::mma_sync(acc, afrag[k], bfrag, acc);
            }
            wmma::store_matrix_sync(dots + rt * 16 * 132 + ct * 16, acc, 132, wmma::mem_row_major);
        }
    }
    __syncthreads();

    // mask + scale pass: dots *= 1/8, self-attention mask by original token id
#pragma unroll
    for (int r = 0; r < 32; r++) {
        int idx = r * 256 + tid;             // 0..8191
        int i = idx >> 7, j = idx & 127;
        float v = dots[i * 132 + j] * 0.125f;
        if (qt[i] == kt[j]) v = -50000.0f;
        dots[i * 132 + j] = v;
    }
    __syncthreads();

    // phase 2: softmax + PV, one pass over j. Thread owns (row i = tid&63, d-quarter).
    // o = (1/s) * sum_j exp(d_j - mx) v_j  ==  sum_j exp(d_j - lse) v_j
    {
        int i = tid & 63, quarter = tid >> 6;    // 0..3, 16 d-elements each
        float mx = -1e30f;
        for (int j = 0; j < 128; j++) mx = fmaxf(mx, dots[i * 132 + j]);

        float s = 0.f;
        float acc[16];
#pragma unroll
        for (int d = 0; d < 16; d++) acc[d] = 0.f;
        for (int j = 0; j < 128; j++) {
            float w = expf(dots[i * 132 + j] - mx);
            s += w;
            const float* vv = &sv[j * 64 + quarter * 16];
#pragma unroll
            for (int d = 0; d < 16; d++) acc[d] += w * vv[d];
        }
        float inv = 1.f / s;
#pragma unroll
        for (int d = 0; d < 16; d++) acc[d] *= inv;

        size_t ro = ((size_t)(base + c * 64 + i)) * 64 + quarter * 16;
        float4* dst = (float4*)(g_so + ro);
#pragma unroll
        for (int q = 0; q < 4; q++)
            dst[q] = make_float4(acc[4 * q], acc[4 * q + 1], acc[4 * q + 2], acc[4 * q + 3]);
        if (quarter == 0) g_lse[base + c * 64 + i] = mx + logf(s);
    }
}

// ---------------- combine hash rounds (softmax over per-round LSE) ----------------
__global__ void combine_kernel() {
    int idx = blockIdx.x * 256 + threadIdx.x;      // m*T_ + t
    int m = idx >> 12, t = idx & (T_ - 1);

    float lg[8]; int gp[8];
#pragma unroll
    for (int h = 0; h < 8; h++) {
        int p = g_pos[(m * NH_ + h) * T_ + t];
        gp[h] = h * T_ + p;
        lg[h] = g_lse[m * NT + gp[h]];
    }
    float mx = lg[0];
#pragma unroll
    for (int h = 1; h < 8; h++) mx = fmaxf(mx, lg[h]);
    float s = 0.f; float w[8];
#pragma unroll
    for (int h = 0; h < 8; h++) { w[h] = expf(lg[h] - mx); s += w[h]; }
    float inv = 1.f / s;

    float out[64];
#pragma unroll
    for (int d = 0; d < 64; d++) out[d] = 0.f;
#pragma unroll
    for (int h = 0; h < 8; h++) {
        const float4* src = (const float4*)(g_so + ((size_t)(m * NT + gp[h])) * 64);
        float ww = w[h] * inv;
#pragma unroll
        for (int q = 0; q < 16; q++) {
            float4 v = src[q];
            out[4 * q + 0] += ww * v.x;
            out[4 * q + 1] += ww * v.y;
            out[4 * q + 2] += ww * v.z;
            out[4 * q + 3] += ww * v.w;
        }
    }
    float4* dst = (float4*)(g_comb + tok_off(m, t));
#pragma unroll
    for (int q = 0; q < 16; q++)
        dst[q] = make_float4(out[4 * q], out[4 * q + 1], out[4 * q + 2], out[4 * q + 3]);
}

// ---------------- launch ----------------
extern "C" void kernel_launch(void* const* d_in, const int* in_sizes, int n_in,
                              void* d_out, int out_size) {
    const float* x     = (const float*)d_in[0];
    const float* w_qk  = (const float*)d_in[1];
    const float* w_v   = (const float*)d_in[2];
    const float* w_out = (const float*)d_in[3];
    const float* b_out = (const float*)d_in[4];
    const float* rot   = (const float*)d_in[5];
    float* out = (float*)d_out;

    float *p_qk, *p_v, *p_comb;
    cudaGetSymbolAddress((void**)&p_qk,   g_qk);
    cudaGetSymbolAddress((void**)&p_v,    g_v);
    cudaGetSymbolAddress((void**)&p_comb, g_comb);

    cudaFuncSetAttribute(attn_kernel, cudaFuncAttributeMaxDynamicSharedMemorySize, ATTN_SMEM);

    dim3 gb(DIM_ / 128, (2 * T_) / 128);   // (8, 64)
    sgemm_xwT<<<gb, 256>>>(x, w_qk, nullptr, p_qk, 2 * T_, DIM_, DIM_, 0);
    sgemm_xwT<<<gb, 256>>>(x, w_v,  nullptr, p_v,  2 * T_, DIM_, DIM_, 0);

    invnorm_kernel<<<(MB * T_) / 256, 256>>>();
    hash_kernel<<<dim3(T_ / 64, MB), 256>>>(rot);
    sort_kernel<<<MB * NH_, 256>>>();

    attn_kernel<<<dim3(NCH, MB), 256, ATTN_SMEM>>>();

    combine_kernel<<<(MB * T_) / 256, 256>>>();
    sgemm_xwT<<<gb, 256>>>(p_comb, w_out, b_out, out, 2 * T_, DIM_, DIM_, 1);
}